// round 7
// baseline (speedup 1.0000x reference)
#include <cuda_runtime.h>
#include <math.h>

// OmegaRule: B=8, L=8192, D=256, W=64 -> NW=128 windows, T=B*W=512 rows/window.
#define BB 8
#define LL 8192
#define DD 256
#define WW 64
#define NW 128
#define TT 512
#define CH 16    // chunks
#define CS 8     // windows per chunk (CH*CS == NW)
#define MATSZ (DD * DD)
#define DUPW 140  // padded row width (floats) for duplicated smem arrays (16B-aligned)
#define BW 68     // padded row width for b-operand smem arrays

// Scratch (device globals; no allocation allowed).
__device__ float g_Skk[NW * MATSZ];
__device__ float g_Svk[NW * MATSZ];
__device__ float g_Ms [NW * MATSZ];
__device__ float g_P  [NW * MATSZ];
__device__ float g_TP0[CH * MATSZ];
__device__ float g_TP1[CH * MATSZ];
__device__ float g_TS0[CH * MATSZ];
__device__ float g_TS1[CH * MATSZ];

typedef unsigned long long u64;
__device__ __forceinline__ void ffma2(u64& acc, u64 a, u64 b) {
    asm("fma.rn.f32x2 %0, %1, %2, %0;" : "+l"(acc) : "l"(a), "l"(b));
}
__device__ __forceinline__ u64 pack2f(float x, float y) {
    u64 r; asm("mov.b64 %0, {%1, %2};" : "=l"(r) : "f"(x), "f"(y)); return r;
}
__device__ __forceinline__ void unpack2f(u64 v, float& x, float& y) {
    asm("mov.b64 {%0, %1}, %2;" : "=f"(x), "=f"(y) : "l"(v));
}
__device__ __forceinline__ float hsum2(u64 v) {
    float x, y; unpack2f(v, x, y); return x + y;
}

// ---------------------------------------------------------------------------
// K1: per-window moment matrices.
//   Skk[n] = sum_t g_t k_t k_t^T (symmetric: ib<=jb computed, mirrored)
//   Svk[n] = sum_t g_t v_t k_t^T (all tiles)
// Duplicated-A FFMA2 microkernel: 8 ffma2 per 16-MAC microstep per matrix.
// grid = (16 tiles, NW), block = 256.
// ---------------------------------------------------------------------------
__global__ __launch_bounds__(256) void k1_moments(
    const float* __restrict__ keys,
    const float* __restrict__ values,
    const float* __restrict__ gammas)
{
    __shared__ float sGKd[16][DUPW];  // gamma*k (x-block), duplicated pairs
    __shared__ float sGVd[16][DUPW];  // gamma*v (x-block), duplicated pairs
    __shared__ float sK  [16][BW];    // k (y-block), plain

    const int n   = blockIdx.y;
    const int ib  = blockIdx.x >> 2;
    const int jb  = blockIdx.x & 3;
    const bool doSkk = (ib <= jb);
    const int tid = threadIdx.x;
    const int tr  = tid >> 4;
    const int tc  = tid & 15;
    const int tx  = tid & 15;
    const int ty  = tid >> 4;

    u64 accV[4][2], accS[4][2];
    #pragma unroll
    for (int r = 0; r < 4; ++r) {
        accV[r][0] = accV[r][1] = 0;
        accS[r][0] = accS[r][1] = 0;
    }

    // prefetch chunk 0
    float g; float4 kx, vx, ky;
    {
        const int b = tr >> 6;   // always 0 here but keep form
        const int t = tr;
        const int w = t & 63;
        const long row = ((long)(t >> 6) * LL + (long)n * WW + w) * DD;
        g  = __ldg(&gammas[(long)(t >> 6) * LL + (long)n * WW + w]);
        (void)b;
        vx = *(const float4*)(values + row + ib * 64 + tc * 4);
        ky = *(const float4*)(keys   + row + jb * 64 + tc * 4);
        kx = *(const float4*)(keys   + row + ib * 64 + tc * 4);
    }

    for (int ch = 0; ch < TT / 16; ++ch) {
        float4 gv = make_float4(g * vx.x, g * vx.y, g * vx.z, g * vx.w);
        ((float4*)&sGVd[tr][0])[tc * 2 + 0] = make_float4(gv.x, gv.x, gv.y, gv.y);
        ((float4*)&sGVd[tr][0])[tc * 2 + 1] = make_float4(gv.z, gv.z, gv.w, gv.w);
        *(float4*)&sK[tr][tc * 4] = ky;
        if (doSkk) {
            float4 gk = make_float4(g * kx.x, g * kx.y, g * kx.z, g * kx.w);
            ((float4*)&sGKd[tr][0])[tc * 2 + 0] = make_float4(gk.x, gk.x, gk.y, gk.y);
            ((float4*)&sGKd[tr][0])[tc * 2 + 1] = make_float4(gk.z, gk.z, gk.w, gk.w);
        }
        __syncthreads();

        if (ch < TT / 16 - 1) {
            const int t = (ch + 1) * 16 + tr;
            const int b = t >> 6;
            const int w = t & 63;
            const long row = ((long)b * LL + (long)n * WW + w) * DD;
            g  = __ldg(&gammas[(long)b * LL + (long)n * WW + w]);
            vx = *(const float4*)(values + row + ib * 64 + tc * 4);
            ky = *(const float4*)(keys   + row + jb * 64 + tc * 4);
            if (doSkk) kx = *(const float4*)(keys + row + ib * 64 + tc * 4);
        }

        if (doSkk) {
            #pragma unroll
            for (int tk = 0; tk < 16; ++tk) {
                const u64* vd = (const u64*)&sGVd[tk][0];
                const u64* kd = (const u64*)&sGKd[tk][0];
                const u64* bp = (const u64*)&sK[tk][tx * 4];
                u64 b0 = bp[0], b1 = bp[1];
                #pragma unroll
                for (int r = 0; r < 4; ++r) {
                    u64 av = vd[ty * 4 + r];
                    u64 ak = kd[ty * 4 + r];
                    ffma2(accV[r][0], av, b0); ffma2(accV[r][1], av, b1);
                    ffma2(accS[r][0], ak, b0); ffma2(accS[r][1], ak, b1);
                }
            }
        } else {
            #pragma unroll
            for (int tk = 0; tk < 16; ++tk) {
                const u64* vd = (const u64*)&sGVd[tk][0];
                const u64* bp = (const u64*)&sK[tk][tx * 4];
                u64 b0 = bp[0], b1 = bp[1];
                #pragma unroll
                for (int r = 0; r < 4; ++r) {
                    u64 av = vd[ty * 4 + r];
                    ffma2(accV[r][0], av, b0); ffma2(accV[r][1], av, b1);
                }
            }
        }
        __syncthreads();
    }

    float* svk = g_Svk + (long)n * MATSZ;
    #pragma unroll
    for (int r = 0; r < 4; ++r) {
        float c0, c1, c2, c3;
        unpack2f(accV[r][0], c0, c1);
        unpack2f(accV[r][1], c2, c3);
        const int x  = ib * 64 + ty * 4 + r;
        const int y0 = jb * 64 + tx * 4;
        *(float4*)(svk + (long)x * DD + y0) = make_float4(c0, c1, c2, c3);
    }
    if (doSkk) {
        float S[4][4];
        #pragma unroll
        for (int r = 0; r < 4; ++r) {
            unpack2f(accS[r][0], S[r][0], S[r][1]);
            unpack2f(accS[r][1], S[r][2], S[r][3]);
        }
        float* skk = g_Skk + (long)n * MATSZ;
        #pragma unroll
        for (int r = 0; r < 4; ++r) {
            const int x  = ib * 64 + ty * 4 + r;
            const int y0 = jb * 64 + tx * 4;
            *(float4*)(skk + (long)x * DD + y0) =
                make_float4(S[r][0], S[r][1], S[r][2], S[r][3]);
        }
        if (ib < jb) {
            #pragma unroll
            for (int r = 0; r < 4; ++r)
                #pragma unroll
                for (int c = 0; c < 4; ++c) {
                    const int x = ib * 64 + ty * 4 + r;
                    const int y = jb * 64 + tx * 4 + c;
                    skk[(long)y * DD + x] = S[r][c];
                }
        }
    }
}

// ---------------------------------------------------------------------------
// Phase A: per-chunk local scan + prefix products (conflict-free col layout).
// At the chunk end also writes the (P,S) summary into tree buffer 0.
// grid = (64 row-groups, CH chunks), block = 256. Thread j owns column j.
// ---------------------------------------------------------------------------
__global__ __launch_bounds__(256) void kA_local(const float* __restrict__ alpha_p)
{
    __shared__ float srow[8][DD];   // rows 0-3: M, rows 4-7: P
    const int j  = threadIdx.x;
    const int c  = blockIdx.y;
    const int o0 = blockIdx.x * 4;
    const float a = 1.f / (1.f + expf(-alpha_p[0]));

    #pragma unroll
    for (int r = 0; r < 4; ++r) {
        srow[r][j] = 0.f;
        srow[4 + r][j] = (j == o0 + r) ? 1.f : 0.f;
    }
    __syncthreads();

    for (int s = 0; s < CS; ++s) {
        const int n = c * CS + s;
        const float* skk = g_Skk + (long)n * MATSZ;
        const float* svk = g_Svk + (long)n * MATSZ;

        const float sv0 = svk[(long)(o0 + 0) * DD + j];
        const float sv1 = svk[(long)(o0 + 1) * DD + j];
        const float sv2 = svk[(long)(o0 + 2) * DD + j];
        const float sv3 = svk[(long)(o0 + 3) * DD + j];

        u64 accM[4] = {0, 0, 0, 0};
        u64 accP[4] = {0, 0, 0, 0};

        float sb[16];
        #pragma unroll
        for (int u = 0; u < 16; ++u) sb[u] = skk[(long)u * DD + j];

        #pragma unroll
        for (int blk = 0; blk < 16; ++blk) {
            float sn[16];
            if (blk < 15) {
                const float* p = skk + (long)(blk + 1) * 16 * DD + j;
                #pragma unroll
                for (int u = 0; u < 16; ++u) sn[u] = p[(long)u * DD];
            } else {
                #pragma unroll
                for (int u = 0; u < 16; ++u) sn[u] = 0.f;
            }
            u64 sp[8];
            #pragma unroll
            for (int p = 0; p < 8; ++p) sp[p] = pack2f(sb[2 * p], sb[2 * p + 1]);

            const int db = blk * 16;
            #pragma unroll
            for (int r = 0; r < 4; ++r) {
                const u64* mrow = (const u64*)&srow[r][db];
                #pragma unroll
                for (int p = 0; p < 8; ++p) ffma2(accM[r], mrow[p], sp[p]);
            }
            #pragma unroll
            for (int r = 0; r < 4; ++r) {
                const u64* prow = (const u64*)&srow[4 + r][db];
                #pragma unroll
                for (int p = 0; p < 8; ++p) ffma2(accP[r], prow[p], sp[p]);
            }
            #pragma unroll
            for (int u = 0; u < 16; ++u) sb[u] = sn[u];
        }

        float nM[4], nP[4];
        const float svv[4] = {sv0, sv1, sv2, sv3};
        #pragma unroll
        for (int r = 0; r < 4; ++r) {
            nM[r] = a * srow[r][j] - hsum2(accM[r]) + svv[r];
            nP[r] = a * srow[4 + r][j] - hsum2(accP[r]);
        }
        __syncthreads();
        float* ms = g_Ms + (long)n * MATSZ;
        float* pp = g_P  + (long)n * MATSZ;
        #pragma unroll
        for (int r = 0; r < 4; ++r) {
            srow[r][j] = nM[r];
            srow[4 + r][j] = nP[r];
            ms[(long)(o0 + r) * DD + j] = nM[r];
            pp[(long)(o0 + r) * DD + j] = nP[r];
        }
        if (s == CS - 1) {   // fused kT_init: chunk summary into tree buffer 0
            float* ts = g_TS0 + (long)c * MATSZ;
            float* tp = g_TP0 + (long)c * MATSZ;
            #pragma unroll
            for (int r = 0; r < 4; ++r) {
                ts[(long)(o0 + r) * DD + j] = nM[r];
                tp[(long)(o0 + r) * DD + j] = nP[r];
            }
        }
        __syncthreads();
    }
}

// ---------------------------------------------------------------------------
// Tree level (Kogge-Stone over chunk summaries):
//   combine(first,second) = (P1@P2, S1@P2 + S2)
// dst_c = combine(src_{c-stride}, src_c) for c>=stride, else copy.
// onlyS=1 at the last level (P result unused). Dup-A FFMA2 microkernel.
// ---------------------------------------------------------------------------
__global__ __launch_bounds__(256) void kT_combine(int stride, int srcIdx, int onlyS)
{
    const float* srcP = srcIdx ? g_TP1 : g_TP0;
    const float* srcS = srcIdx ? g_TS1 : g_TS0;
    float*       dstP = srcIdx ? g_TP0 : g_TP1;
    float*       dstS = srcIdx ? g_TS0 : g_TS1;

    const int c   = blockIdx.y;
    const int isS = onlyS ? 1 : blockIdx.z;
    const int ib  = blockIdx.x >> 2;
    const int jb  = blockIdx.x & 3;
    const int tid = threadIdx.x;

    const float* srcM = isS ? srcS : srcP;
    float*       dstM = isS ? dstS : dstP;

    if (c < stride) {   // pass-through copy
        const int lr = tid >> 2;
        const int lc = tid & 3;
        const long base = (long)c * MATSZ;
        #pragma unroll
        for (int it = 0; it < 4; ++it) {
            const long off = base + (long)(ib * 64 + lr) * DD + jb * 64 + (lc + it * 4) * 4;
            *(float4*)(dstM + off) = *(const float4*)(srcM + off);
        }
        return;
    }

    __shared__ float sAd[16][DUPW];   // A rows duplicated, transposed by d
    __shared__ float sB [16][BW];

    const int lr = tid >> 2;
    const int lc = tid & 3;
    const int pr = tid >> 4;
    const int pc = tid & 15;
    const int tx = tid & 15;
    const int ty = tid >> 4;

    const float* A  = srcM + (long)(c - stride) * MATSZ;  // S_{c-s} or P_{c-s}
    const float* Bm = srcP + (long)c * MATSZ;             // P_c
    float*       Dm = dstM + (long)c * MATSZ;

    u64 acc[4][2];
    #pragma unroll
    for (int r = 0; r < 4; ++r) { acc[r][0] = 0; acc[r][1] = 0; }

    const long arow = (long)(ib * 64 + lr) * DD;

    float4 av = *(const float4*)(A + arow + lc * 4);
    float4 bv = *(const float4*)(Bm + (long)pr * DD + jb * 64 + pc * 4);

    for (int ch = 0; ch < 16; ++ch) {
        *(float2*)&sAd[lc * 4 + 0][lr * 2] = make_float2(av.x, av.x);
        *(float2*)&sAd[lc * 4 + 1][lr * 2] = make_float2(av.y, av.y);
        *(float2*)&sAd[lc * 4 + 2][lr * 2] = make_float2(av.z, av.z);
        *(float2*)&sAd[lc * 4 + 3][lr * 2] = make_float2(av.w, av.w);
        *(float4*)&sB[pr][pc * 4] = bv;
        __syncthreads();

        if (ch < 15) {
            av = *(const float4*)(A + arow + (ch + 1) * 16 + lc * 4);
            bv = *(const float4*)(Bm + (long)((ch + 1) * 16 + pr) * DD + jb * 64 + pc * 4);
        }

        #pragma unroll
        for (int dk = 0; dk < 16; ++dk) {
            const u64* ad = (const u64*)&sAd[dk][0];
            const u64* bp = (const u64*)&sB[dk][tx * 4];
            u64 b0 = bp[0], b1 = bp[1];
            #pragma unroll
            for (int r = 0; r < 4; ++r) {
                u64 aa = ad[ty * 4 + r];
                ffma2(acc[r][0], aa, b0);
                ffma2(acc[r][1], aa, b1);
            }
        }
        __syncthreads();
    }

    const float* C0 = srcS + (long)c * MATSZ;
    #pragma unroll
    for (int r = 0; r < 4; ++r) {
        float c0, c1, c2, c3;
        unpack2f(acc[r][0], c0, c1);
        unpack2f(acc[r][1], c2, c3);
        const long off = (long)(ib * 64 + ty * 4 + r) * DD + jb * 64 + tx * 4;
        float4 res = make_float4(c0, c1, c2, c3);
        if (isS) {
            float4 cc = *(const float4*)(C0 + off);
            res.x += cc.x; res.y += cc.y; res.z += cc.z; res.w += cc.w;
        }
        *(float4*)(Dm + off) = res;
    }
}

// ---------------------------------------------------------------------------
// Phase C: fix-up GEMMs: Ms[n] += E_{c-1} @ P_n for chunks 1..CH-1.
// E = g_TS0 (final tree buffer). Dup-A FFMA2 microkernel.
// ---------------------------------------------------------------------------
__global__ __launch_bounds__(256) void kC_fix()
{
    __shared__ float sEd[16][DUPW];
    __shared__ float sP [16][BW];

    const int nw  = blockIdx.y + CS;
    const int c   = nw / CS;
    const int ib  = blockIdx.x >> 2;
    const int jb  = blockIdx.x & 3;
    const int tid = threadIdx.x;
    const int lr  = tid >> 2;
    const int lc  = tid & 3;
    const int pr  = tid >> 4;
    const int pc  = tid & 15;
    const int tx  = tid & 15;
    const int ty  = tid >> 4;

    const float* E = g_TS0 + (long)(c - 1) * MATSZ;
    const float* P = g_P + (long)nw * MATSZ;
    float*      Ms = g_Ms + (long)nw * MATSZ;

    u64 acc[4][2];
    #pragma unroll
    for (int r = 0; r < 4; ++r) { acc[r][0] = 0; acc[r][1] = 0; }

    const long erow = (long)(ib * 64 + lr) * DD;

    float4 ev = *(const float4*)(E + erow + lc * 4);
    float4 pv = *(const float4*)(P + (long)pr * DD + jb * 64 + pc * 4);

    for (int ch = 0; ch < 16; ++ch) {
        *(float2*)&sEd[lc * 4 + 0][lr * 2] = make_float2(ev.x, ev.x);
        *(float2*)&sEd[lc * 4 + 1][lr * 2] = make_float2(ev.y, ev.y);
        *(float2*)&sEd[lc * 4 + 2][lr * 2] = make_float2(ev.z, ev.z);
        *(float2*)&sEd[lc * 4 + 3][lr * 2] = make_float2(ev.w, ev.w);
        *(float4*)&sP[pr][pc * 4] = pv;
        __syncthreads();

        if (ch < 15) {
            ev = *(const float4*)(E + erow + (ch + 1) * 16 + lc * 4);
            pv = *(const float4*)(P + (long)((ch + 1) * 16 + pr) * DD + jb * 64 + pc * 4);
        }

        #pragma unroll
        for (int dk = 0; dk < 16; ++dk) {
            const u64* ad = (const u64*)&sEd[dk][0];
            const u64* bp = (const u64*)&sP[dk][tx * 4];
            u64 b0 = bp[0], b1 = bp[1];
            #pragma unroll
            for (int r = 0; r < 4; ++r) {
                u64 aa = ad[ty * 4 + r];
                ffma2(acc[r][0], aa, b0);
                ffma2(acc[r][1], aa, b1);
            }
        }
        __syncthreads();
    }

    #pragma unroll
    for (int r = 0; r < 4; ++r) {
        float c0, c1, c2, c3;
        unpack2f(acc[r][0], c0, c1);
        unpack2f(acc[r][1], c2, c3);
        float* dst = Ms + (long)(ib * 64 + ty * 4 + r) * DD + jb * 64 + tx * 4;
        float4 old = *(const float4*)dst;
        *(float4*)dst = make_float4(old.x + c0, old.y + c1, old.z + c2, old.w + c3);
    }
}

// ---------------------------------------------------------------------------
// K3: retrieval. out[t][o] = sum_d q[t][d] * Ms[n][o][d]
// Dup-A FFMA2 microkernel (a = q rows duplicated, b = M rows transposed by d).
// ---------------------------------------------------------------------------
__global__ __launch_bounds__(256) void k3_out(
    const float* __restrict__ queries, float* __restrict__ out)
{
    __shared__ float sQd[16][DUPW];
    __shared__ float sM [16][BW];

    const int n   = blockIdx.y;
    const int tb  = blockIdx.x >> 2;
    const int ob  = blockIdx.x & 3;
    const int tid = threadIdx.x;
    const int lr  = tid >> 2;
    const int lc  = tid & 3;
    const int tx  = tid & 15;
    const int ty  = tid >> 4;

    const float* Ms = g_Ms + (long)n * MATSZ;

    u64 acc[4][2];
    #pragma unroll
    for (int r = 0; r < 4; ++r) { acc[r][0] = 0; acc[r][1] = 0; }

    const int t_ld = tb * 64 + lr;
    const int b_ld = t_ld >> 6;
    const int w_ld = t_ld & 63;
    const long qrow = ((long)b_ld * LL + (long)n * WW + w_ld) * DD;
    const long mrow = (long)(ob * 64 + lr) * DD;

    float4 qv = *(const float4*)(queries + qrow + lc * 4);
    float4 mv = *(const float4*)(Ms + mrow + lc * 4);

    for (int ch = 0; ch < 16; ++ch) {
        *(float2*)&sQd[lc * 4 + 0][lr * 2] = make_float2(qv.x, qv.x);
        *(float2*)&sQd[lc * 4 + 1][lr * 2] = make_float2(qv.y, qv.y);
        *(float2*)&sQd[lc * 4 + 2][lr * 2] = make_float2(qv.z, qv.z);
        *(float2*)&sQd[lc * 4 + 3][lr * 2] = make_float2(qv.w, qv.w);
        sM[lc * 4 + 0][lr] = mv.x; sM[lc * 4 + 1][lr] = mv.y;
        sM[lc * 4 + 2][lr] = mv.z; sM[lc * 4 + 3][lr] = mv.w;
        __syncthreads();

        if (ch < 15) {
            qv = *(const float4*)(queries + qrow + (ch + 1) * 16 + lc * 4);
            mv = *(const float4*)(Ms + mrow + (ch + 1) * 16 + lc * 4);
        }

        #pragma unroll
        for (int dk = 0; dk < 16; ++dk) {
            const u64* ad = (const u64*)&sQd[dk][0];
            const u64* bp = (const u64*)&sM[dk][tx * 4];
            u64 b0 = bp[0], b1 = bp[1];
            #pragma unroll
            for (int r = 0; r < 4; ++r) {
                u64 aa = ad[ty * 4 + r];
                ffma2(acc[r][0], aa, b0);
                ffma2(acc[r][1], aa, b1);
            }
        }
        __syncthreads();
    }

    #pragma unroll
    for (int r = 0; r < 4; ++r) {
        float c0, c1, c2, c3;
        unpack2f(acc[r][0], c0, c1);
        unpack2f(acc[r][1], c2, c3);
        const int t = tb * 64 + ty * 4 + r;
        const int b = t >> 6;
        const int w = t & 63;
        const long addr = ((long)b * LL + (long)n * WW + w) * DD + ob * 64 + tx * 4;
        *(float4*)(out + addr) = make_float4(c0, c1, c2, c3);
    }
}

// ---------------------------------------------------------------------------
extern "C" void kernel_launch(void* const* d_in, const int* in_sizes, int n_in,
                              void* d_out, int out_size)
{
    const float* keys    = (const float*)d_in[0];
    const float* values  = (const float*)d_in[1];
    const float* queries = (const float*)d_in[2];
    const float* gammas  = (const float*)d_in[3];
    const float* alpha   = (const float*)d_in[4];
    float* out = (float*)d_out;

    k1_moments<<<dim3(16, NW), 256>>>(keys, values, gammas);
    kA_local<<<dim3(64, CH), 256>>>(alpha);
    kT_combine<<<dim3(16, CH, 2), 256>>>(1, 0, 0);  // buf0 -> buf1
    kT_combine<<<dim3(16, CH, 2), 256>>>(2, 1, 0);  // buf1 -> buf0
    kT_combine<<<dim3(16, CH, 2), 256>>>(4, 0, 0);  // buf0 -> buf1
    kT_combine<<<dim3(16, CH, 1), 256>>>(8, 1, 1);  // buf1 -> buf0, S only
    kC_fix<<<dim3(16, NW - CS), 256>>>();
    k3_out<<<dim3(32, NW), 256>>>(queries, out);
}